// round 6
// baseline (speedup 1.0000x reference)
#include <cuda_runtime.h>
#include <math.h>
#include <stdint.h>

#define BATCH 32
#define CIN   256
#define OHW   28
#define HW    784          // 28*28
#define IH    56
#define IHW   3136         // 56*56
#define MFUSE 352          // 128 + 192 + 32 stacked branch-weight rows

// ---------------- scratch (static device arrays; no cudaMalloc) ----------------
__device__ float g_f1r [BATCH * CIN * HW];
__device__ float g_f2r [BATCH * CIN * HW];
__device__ float g_mpool[BATCH * HW];
__device__ float g_scale[BATCH * HW];
__device__ float g_corr [(size_t)BATCH * HW * HW];
__device__ float g_y2a  [BATCH * 192 * HW];
__device__ float g_y3a  [BATCH *  32 * HW];
__device__ float g_y    [BATCH * 512 * HW];
__device__ float g_mean [512];
__device__ float g_inv  [512];
__device__ float g_Wpk  [MFUSE * HW];
__device__ float g_bpk  [MFUSE];

// ---------------- bilinear resize 56->28, align_corners=True ----------------
__global__ void resize_k(const float* __restrict__ f1, const float* __restrict__ f2) {
    int idx = blockIdx.x * blockDim.x + threadIdx.x;
    const int total = BATCH * CIN * HW;
    if (idx >= 2 * total) return;
    const float* src = (idx < total) ? f1 : f2;
    float* dst       = (idx < total) ? g_f1r : g_f2r;
    int i  = (idx < total) ? idx : idx - total;
    int q  = i % HW;
    int bc = i / HW;
    int oy = q / OHW, ox = q % OHW;
    const float step = 55.0f / 27.0f;
    float fy = oy * step, fx = ox * step;
    int y0 = (int)floorf(fy); if (y0 > IH - 1) y0 = IH - 1;
    int x0 = (int)floorf(fx); if (x0 > IH - 1) x0 = IH - 1;
    int y1 = min(y0 + 1, IH - 1);
    int x1 = min(x0 + 1, IH - 1);
    float wy = fy - (float)y0;
    float wx = fx - (float)x0;
    const float* p = src + (size_t)bc * IHW;
    float v00 = p[y0 * IH + x0], v01 = p[y0 * IH + x1];
    float v10 = p[y1 * IH + x0], v11 = p[y1 * IH + x1];
    float r0 = v00 * (1.0f - wy) + v10 * wy;
    float r1 = v01 * (1.0f - wy) + v11 * wy;
    dst[i] = r0 * (1.0f - wx) + r1 * wx;
}

// ---------------- mask maxpool 2x2 s2 ----------------
__global__ void mpool_k(const float* __restrict__ mask) {
    int idx = blockIdx.x * blockDim.x + threadIdx.x;
    if (idx >= BATCH * HW) return;
    int b = idx / HW, q = idx % HW;
    int y = q / OHW, x = q % OHW;
    const float* p = mask + (size_t)b * IHW;
    float m0 = p[(2*y)   * IH + 2*x], m1 = p[(2*y)   * IH + 2*x + 1];
    float m2 = p[(2*y+1) * IH + 2*x], m3 = p[(2*y+1) * IH + 2*x + 1];
    g_mpool[idx] = fmaxf(fmaxf(m0, m1), fmaxf(m2, m3));
}

// ---------------- pack branch weights into one stacked matrix ----------------
__global__ void pack_k(const float* __restrict__ W1,  const float* __restrict__ b1,
                       const float* __restrict__ W2a, const float* __restrict__ b2a,
                       const float* __restrict__ W3a, const float* __restrict__ b3a) {
    int idx = blockIdx.x * blockDim.x + threadIdx.x;
    if (idx < MFUSE * HW) {
        int m = idx / HW, k = idx % HW;
        float v;
        if (m < 128)      v = W1 [(size_t)m * HW + k];
        else if (m < 320) v = W2a[(size_t)(m - 128) * HW + k];
        else              v = W3a[(size_t)(m - 320) * HW + k];
        g_Wpk[idx] = v;
    }
    if (idx < MFUSE) {
        float v;
        if (idx < 128)      v = b1 [idx];
        else if (idx < 320) v = b2a[idx - 128];
        else                v = b3a[idx - 320];
        g_bpk[idx] = v;
    }
}

// ---------------- tf32 split helpers ----------------
__device__ __forceinline__ void split_tf32(float v, uint32_t& hi, uint32_t& lo) {
    asm("cvt.rna.tf32.f32 %0, %1;" : "=r"(hi) : "f"(v));
    float r = v - __uint_as_float(hi);
    asm("cvt.rna.tf32.f32 %0, %1;" : "=r"(lo) : "f"(r));
}

#define MMA_TF32(d, a, b)                                                      \
    asm volatile("mma.sync.aligned.m16n8k8.row.col.f32.tf32.tf32.f32 "         \
        "{%0,%1,%2,%3}, {%4,%5,%6,%7}, {%8,%9}, {%0,%1,%2,%3};"                \
        : "+f"((d)[0]), "+f"((d)[1]), "+f"((d)[2]), "+f"((d)[3])               \
        : "r"((a)[0]), "r"((a)[1]), "r"((a)[2]), "r"((a)[3]),                  \
          "r"((b)[0]), "r"((b)[1]))

// =====================================================================
// 128x128x8 double-buffered GEMM, 256 threads, tensor-core tf32 3x core.
// C[b][m][n] = relu( epiScale?[b][n] * (sum_k A.B) + bias?[m] )
// MODE: 0 = plain B[k][n];  3/5 = conv im2col decode;  9 = fused 3x3 maxpool
// WA: true -> A is weights [m][k]; false -> A[k][m]
// ROUTE: true -> A = g_Wpk, bias = g_bpk, outputs routed per m to y/y2a/y3a
// =====================================================================
template <int MODE, bool WA, bool ROUTE>
__global__ __launch_bounds__(256)
void gemm_k(const float* __restrict__ A, const float* __restrict__ Bm,
            float* __restrict__ C,
            int M, int N, int K,
            long aB, long bB, long cB,
            int sAk, int sAm,
            const float* __restrict__ scale,
            const float* __restrict__ bias,
            int cStride)
{
    const int b = blockIdx.z;
    const float* Ab = ROUTE ? g_Wpk : (A + (size_t)b * aB);
    const float* Bb = Bm + (size_t)b * bB;
    float*       Cb = C  + (size_t)b * cB;
    const float* scb = scale ? scale + (size_t)b * HW : (const float*)0;

    const int m0 = blockIdx.y * 128;
    const int n0 = blockIdx.x * 128;

    __shared__ uint32_t As_hi[2][8][132];
    __shared__ uint32_t As_lo[2][8][132];
    __shared__ uint32_t Bs_hi[2][8][132];
    __shared__ uint32_t Bs_lo[2][8][132];

    const int tid  = threadIdx.x;
    const int wid  = tid >> 5;
    const int lane = tid & 31;
    const int gid  = lane >> 2;      // 0..7
    const int tig  = lane & 3;       // 0..3
    const int wm   = (wid & 1) * 64; // warp m offset
    const int wn   = (wid >> 1) * 32;// warp n offset

    // loader indices
    const int a_k  = tid >> 5;            // act mode: k row 0..7
    const int a_m4 = (tid & 31) * 4;      // act mode: m col
    const int aw_m = tid >> 1;            // weight mode: m 0..127
    const int aw_k = (tid & 1) * 4;       // weight mode: k offset 0 or 4
    const int b_k  = tid >> 5;
    const int b_n4 = (tid & 31) * 4;

    float4 avr, bvr;
    const float4 f4z = make_float4(0.f, 0.f, 0.f, 0.f);

#define LOAD_A(K0)                                                              \
    {                                                                           \
        avr = f4z;                                                              \
        if (WA) {                                                               \
            if (m0 + aw_m < M)                                                  \
                avr = *(const float4*)&Ab[(size_t)(m0 + aw_m) * sAm + (K0) + aw_k]; \
        } else {                                                                \
            if (m0 + a_m4 < M)                                                  \
                avr = *(const float4*)&Ab[(size_t)((K0) + a_k) * sAk + m0 + a_m4]; \
        }                                                                       \
    }

#define STORE_A(BUF)                                                            \
    {                                                                           \
        uint32_t h0,l0,h1,l1,h2,l2,h3,l3;                                       \
        split_tf32(avr.x, h0, l0); split_tf32(avr.y, h1, l1);                   \
        split_tf32(avr.z, h2, l2); split_tf32(avr.w, h3, l3);                   \
        if (WA) {                                                               \
            As_hi[BUF][aw_k + 0][aw_m] = h0;  As_lo[BUF][aw_k + 0][aw_m] = l0;  \
            As_hi[BUF][aw_k + 1][aw_m] = h1;  As_lo[BUF][aw_k + 1][aw_m] = l1;  \
            As_hi[BUF][aw_k + 2][aw_m] = h2;  As_lo[BUF][aw_k + 2][aw_m] = l2;  \
            As_hi[BUF][aw_k + 3][aw_m] = h3;  As_lo[BUF][aw_k + 3][aw_m] = l3;  \
        } else {                                                                \
            uint4 hv = make_uint4(h0, h1, h2, h3);                              \
            uint4 lv = make_uint4(l0, l1, l2, l3);                              \
            *(uint4*)&As_hi[BUF][a_k][a_m4] = hv;                               \
            *(uint4*)&As_lo[BUF][a_k][a_m4] = lv;                               \
        }                                                                       \
    }

#define LOAD_B(K0)                                                              \
    {                                                                           \
        if (MODE == 0) {                                                        \
            bvr = f4z;                                                          \
            if (n0 + b_n4 < N)                                                  \
                bvr = *(const float4*)&Bb[(size_t)((K0) + b_k) * N + n0 + b_n4];\
        } else if (MODE == 9) {                                                 \
            const int gk = (K0) + b_k;                                          \
            const float* row = Bb + (size_t)gk * HW;                            \
            float vv[4];                                                        \
            _Pragma("unroll")                                                   \
            for (int j = 0; j < 4; j++) {                                       \
                int gn = n0 + b_n4 + j;                                         \
                float mx = 0.0f;                                                \
                if (gn < N) {                                                   \
                    int y = gn / OHW, x = gn % OHW;                             \
                    mx = -INFINITY;                                             \
                    _Pragma("unroll")                                           \
                    for (int dy = -1; dy <= 1; dy++) {                          \
                        int iy = y + dy;                                        \
                        if (iy < 0 || iy >= OHW) continue;                      \
                        _Pragma("unroll")                                       \
                        for (int dx = -1; dx <= 1; dx++) {                      \
                            int ix = x + dx;                                    \
                            if (ix < 0 || ix >= OHW) continue;                  \
                            int qq = iy * OHW + ix;                             \
                            mx = fmaxf(mx, row[qq] * scb[qq]);                  \
                        }                                                       \
                    }                                                           \
                }                                                               \
                vv[j] = mx;                                                     \
            }                                                                   \
            bvr = make_float4(vv[0], vv[1], vv[2], vv[3]);                      \
        } else {                                                                \
            const int kk2 = MODE * MODE;                                        \
            const int pad = MODE / 2;                                           \
            const int gk = (K0) + b_k;                                          \
            const int c  = gk / kk2;                                            \
            const int r  = gk % kk2;                                            \
            const int ky = r / MODE, kx = r % MODE;                             \
            float vv[4];                                                        \
            _Pragma("unroll")                                                   \
            for (int j = 0; j < 4; j++) {                                       \
                int gn = n0 + b_n4 + j;                                         \
                float v = 0.0f;                                                 \
                if (gn < N) {                                                   \
                    int y = gn / OHW + ky - pad;                                \
                    int x = gn % OHW + kx - pad;                                \
                    if (y >= 0 && y < OHW && x >= 0 && x < OHW)                 \
                        v = Bb[c * HW + y * OHW + x];                           \
                }                                                               \
                vv[j] = v;                                                      \
            }                                                                   \
            bvr = make_float4(vv[0], vv[1], vv[2], vv[3]);                      \
        }                                                                       \
    }

#define STORE_B(BUF)                                                            \
    {                                                                           \
        uint32_t h0,l0,h1,l1,h2,l2,h3,l3;                                       \
        split_tf32(bvr.x, h0, l0); split_tf32(bvr.y, h1, l1);                   \
        split_tf32(bvr.z, h2, l2); split_tf32(bvr.w, h3, l3);                   \
        uint4 hv = make_uint4(h0, h1, h2, h3);                                  \
        uint4 lv = make_uint4(l0, l1, l2, l3);                                  \
        *(uint4*)&Bs_hi[BUF][b_k][b_n4] = hv;                                   \
        *(uint4*)&Bs_lo[BUF][b_k][b_n4] = lv;                                   \
    }

    float d[4][4][4];   // [mf][nf][reg]
#pragma unroll
    for (int i = 0; i < 4; i++)
#pragma unroll
        for (int j = 0; j < 4; j++)
#pragma unroll
            for (int r = 0; r < 4; r++) d[i][j][r] = 0.0f;

    const int nt = K >> 3;

    LOAD_A(0); LOAD_B(0);
    STORE_A(0); STORE_B(0);
    __syncthreads();

    for (int t = 0; t < nt; t++) {
        const int buf = t & 1;
        if (t + 1 < nt) { LOAD_A((t + 1) * 8); LOAD_B((t + 1) * 8); }

        // fragment loads (conflict-free thanks to 132 padding)
        uint32_t ahi[4][4], alo[4][4], bhi[4][2], blo[4][2];
#pragma unroll
        for (int mf = 0; mf < 4; mf++) {
            int mb = wm + mf * 16 + gid;
            ahi[mf][0] = As_hi[buf][tig    ][mb];
            ahi[mf][1] = As_hi[buf][tig    ][mb + 8];
            ahi[mf][2] = As_hi[buf][tig + 4][mb];
            ahi[mf][3] = As_hi[buf][tig + 4][mb + 8];
            alo[mf][0] = As_lo[buf][tig    ][mb];
            alo[mf][1] = As_lo[buf][tig    ][mb + 8];
            alo[mf][2] = As_lo[buf][tig + 4][mb];
            alo[mf][3] = As_lo[buf][tig + 4][mb + 8];
        }
#pragma unroll
        for (int nf = 0; nf < 4; nf++) {
            int nb = wn + nf * 8 + gid;
            bhi[nf][0] = Bs_hi[buf][tig    ][nb];
            bhi[nf][1] = Bs_hi[buf][tig + 4][nb];
            blo[nf][0] = Bs_lo[buf][tig    ][nb];
            blo[nf][1] = Bs_lo[buf][tig + 4][nb];
        }

#pragma unroll
        for (int mf = 0; mf < 4; mf++)
#pragma unroll
            for (int nf = 0; nf < 4; nf++) {
                MMA_TF32(d[mf][nf], ahi[mf], bhi[nf]);
                MMA_TF32(d[mf][nf], ahi[mf], blo[nf]);
                MMA_TF32(d[mf][nf], alo[mf], bhi[nf]);
            }

        if (t + 1 < nt) { STORE_A(buf ^ 1); STORE_B(buf ^ 1); }
        __syncthreads();
    }

    // ---- epilogue ----
#pragma unroll
    for (int mf = 0; mf < 4; mf++) {
#pragma unroll
        for (int half = 0; half < 2; half++) {
            int m = m0 + wm + mf * 16 + gid + half * 8;
            if (m >= M) continue;
            float bi;
            float* outp;
            if (ROUTE) {
                bi = g_bpk[m];
                if (m < 128)      outp = g_y   + (size_t)b * 512 * HW + (size_t)m * HW;
                else if (m < 320) outp = g_y2a + (size_t)b * 192 * HW + (size_t)(m - 128) * HW;
                else              outp = g_y3a + (size_t)b *  32 * HW + (size_t)(m - 320) * HW;
            } else {
                bi = bias ? bias[m] : 0.0f;
                outp = Cb + (size_t)m * cStride;
            }
#pragma unroll
            for (int nf = 0; nf < 4; nf++) {
                int n = n0 + wn + nf * 8 + 2 * tig;
                float v0 = d[mf][nf][half * 2 + 0];
                float v1 = d[mf][nf][half * 2 + 1];
                if (n < N) {
                    float v = v0;
                    if (MODE != 9 && scale) v *= scb[n];
                    outp[n] = fmaxf(v + bi, 0.0f);
                }
                if (n + 1 < N) {
                    float v = v1;
                    if (MODE != 9 && scale) v *= scb[n + 1];
                    outp[n + 1] = fmaxf(v + bi, 0.0f);
                }
            }
        }
    }
#undef LOAD_A
#undef STORE_A
#undef LOAD_B
#undef STORE_B
}

// ---------------- per-column L2 norm of corr -> scale = mask / norm ----------------
__global__ void norm_k() {
    int idx = blockIdx.x * blockDim.x + threadIdx.x;
    if (idx >= BATCH * HW) return;
    int b = idx / HW, q = idx % HW;
    const float* base = g_corr + (size_t)b * HW * HW + q;
    float s0 = 0.f, s1 = 0.f, s2 = 0.f, s3 = 0.f;
    for (int p = 0; p + 4 <= HW; p += 4) {
        float v0 = base[(size_t)(p    ) * HW];
        float v1 = base[(size_t)(p + 1) * HW];
        float v2 = base[(size_t)(p + 2) * HW];
        float v3 = base[(size_t)(p + 3) * HW];
        s0 += v0 * v0; s1 += v1 * v1; s2 += v2 * v2; s3 += v3 * v3;
    }
    float s = (s0 + s1) + (s2 + s3);
    g_scale[idx] = g_mpool[idx] / sqrtf(s);
}

// ---------------- batchnorm stats (training-mode, biased var) ----------------
__global__ void bnstat_k() {
    const int ch  = blockIdx.x;
    const int tid = threadIdx.x;
    const int NEL = BATCH * HW;
    double s = 0.0, ss = 0.0;
    for (int i = tid; i < NEL; i += blockDim.x) {
        int b = i / HW, q = i % HW;
        float v = g_y[(size_t)b * 512 * HW + (size_t)ch * HW + q];
        s  += (double)v;
        ss += (double)v * (double)v;
    }
    __shared__ double sh[256];
    __shared__ double sh2[256];
    sh[tid] = s; sh2[tid] = ss;
    __syncthreads();
    for (int st = 128; st > 0; st >>= 1) {
        if (tid < st) { sh[tid] += sh[tid + st]; sh2[tid] += sh2[tid + st]; }
        __syncthreads();
    }
    if (tid == 0) {
        double mean = sh[0] / NEL;
        double var  = sh2[0] / NEL - mean * mean;
        g_mean[ch] = (float)mean;
        g_inv[ch]  = (float)(1.0 / sqrt(var + 1e-5));
    }
}

__global__ void bnapply_k(const float* __restrict__ gamma,
                          const float* __restrict__ beta,
                          float* __restrict__ out) {
    int idx = blockIdx.x * blockDim.x + threadIdx.x;
    if (idx >= BATCH * 512 * HW) return;
    int ch = (idx / HW) % 512;
    out[idx] = gamma[ch] * (g_y[idx] - g_mean[ch]) * g_inv[ch] + beta[ch];
}

// ---------------- launch ----------------
static float* sym_addr(const void* symbol) {
    void* p = nullptr;
    cudaGetSymbolAddress(&p, symbol);
    return (float*)p;
}

extern "C" void kernel_launch(void* const* d_in, const int* in_sizes, int n_in,
                              void* d_out, int out_size) {
    const float* feature1 = (const float*)d_in[0];
    const float* feature2 = (const float*)d_in[1];
    const float* mask     = (const float*)d_in[2];
    const float* W1  = (const float*)d_in[3];
    const float* b1  = (const float*)d_in[4];
    const float* W2a = (const float*)d_in[5];
    const float* b2a = (const float*)d_in[6];
    const float* W2b = (const float*)d_in[7];
    const float* b2b = (const float*)d_in[8];
    const float* W3a = (const float*)d_in[9];
    const float* b3a = (const float*)d_in[10];
    const float* W3b = (const float*)d_in[11];
    const float* b3b = (const float*)d_in[12];
    const float* W4  = (const float*)d_in[13];
    const float* b4  = (const float*)d_in[14];
    const float* gamma = (const float*)d_in[15];
    const float* beta  = (const float*)d_in[16];
    float* out = (float*)d_out;

    float* f1r  = sym_addr(g_f1r);
    float* f2r  = sym_addr(g_f2r);
    float* corr = sym_addr(g_corr);
    float* scal = sym_addr(g_scale);
    float* y2a  = sym_addr(g_y2a);
    float* y3a  = sym_addr(g_y3a);
    float* ybuf = sym_addr(g_y);

    // 1) resize both features
    {
        int total = 2 * BATCH * CIN * HW;
        resize_k<<<(total + 255) / 256, 256>>>(feature1, feature2);
    }
    // 2) mask maxpool + weight packing
    mpool_k<<<(BATCH * HW + 255) / 256, 256>>>(mask);
    pack_k<<<(MFUSE * HW + 255) / 256, 256>>>(W1, b1, W2a, b2a, W3a, b3a);

    // 3) correlation GEMM
    {
        dim3 grid(7, 7, BATCH);
        gemm_k<0, false, false><<<grid, 256>>>(f1r, f2r, corr,
                                               HW, HW, CIN,
                                               (long)CIN * HW, (long)CIN * HW, (long)HW * HW,
                                               HW, 1, nullptr, nullptr, HW);
    }
    // 4) column L2 norm -> scale
    norm_k<<<(BATCH * HW + 255) / 256, 256>>>();

    // 5) fused branch GEMM: W1|W2a|W3a (M=352), scale folded in epilogue
    {
        dim3 g(7, 3, BATCH);
        gemm_k<0, true, true><<<g, 256>>>(nullptr, corr, nullptr,
                                          MFUSE, HW, HW,
                                          0L, (long)HW * HW, 0L,
                                          1, HW, scal, nullptr, HW);
    }
    // 6) W4 on 3x3-maxpooled scaled corr (pool fused in B loader)
    {
        dim3 g(7, 1, BATCH);
        gemm_k<9, true, false><<<g, 256>>>(W4, corr, ybuf + (size_t)448 * HW,
                                           64, HW, HW,
                                           0L, (long)HW * HW, (long)512 * HW,
                                           1, HW, scal, b4, HW);
    }
    // 7) 3x3 conv 192->256 (implicit GEMM)
    {
        dim3 g(7, 2, BATCH);
        gemm_k<3, true, false><<<g, 256>>>(W2b, y2a, ybuf + (size_t)128 * HW,
                                           256, HW, 192 * 9,
                                           0L, (long)192 * HW, (long)512 * HW,
                                           1, 192 * 9, nullptr, b2b, HW);
    }
    // 8) 5x5 conv 32->64 (implicit GEMM)
    {
        dim3 g(7, 1, BATCH);
        gemm_k<5, true, false><<<g, 256>>>(W3b, y3a, ybuf + (size_t)384 * HW,
                                           64, HW, 32 * 25,
                                           0L, (long)32 * HW, (long)512 * HW,
                                           1, 32 * 25, nullptr, b3b, HW);
    }
    // 9) batchnorm stats + apply
    bnstat_k<<<512, 256>>>();
    {
        int total = BATCH * 512 * HW;
        bnapply_k<<<(total + 255) / 256, 256>>>(gamma, beta, out);
    }
}

// round 10
// speedup vs baseline: 1.7416x; 1.7416x over previous
#include <cuda_runtime.h>
#include <cuda_bf16.h>
#include <math.h>
#include <stdint.h>

#define BATCH 32
#define CIN   256
#define OHW   28
#define HW    784          // 28*28
#define IH    56
#define IHW   3136         // 56*56
#define MFUSE 352          // 128 + 192 + 32

// ---------------- scratch ----------------
__device__ float g_f1r [BATCH * CIN * HW];
__device__ float g_f2r [BATCH * CIN * HW];
__device__ float g_mpool[BATCH * HW];
__device__ float g_scale[BATCH * HW];
__device__ float g_corr [(size_t)BATCH * HW * HW];
__device__ float g_y2a  [BATCH * 192 * HW];
__device__ float g_y3a  [BATCH *  32 * HW];
__device__ float g_y    [BATCH * 512 * HW];
__device__ float g_mean [512];
__device__ float g_inv  [512];
__device__ float g_Wpk  [MFUSE * HW];
__device__ float g_bpk  [MFUSE];

// ---------------- bilinear resize 56->28, align_corners=True ----------------
__global__ void resize_k(const float* __restrict__ f1, const float* __restrict__ f2) {
    int idx = blockIdx.x * blockDim.x + threadIdx.x;
    const int total = BATCH * CIN * HW;
    if (idx >= 2 * total) return;
    const float* src = (idx < total) ? f1 : f2;
    float* dst       = (idx < total) ? g_f1r : g_f2r;
    int i  = (idx < total) ? idx : idx - total;
    int q  = i % HW;
    int bc = i / HW;
    int oy = q / OHW, ox = q % OHW;
    const float step = 55.0f / 27.0f;
    float fy = oy * step, fx = ox * step;
    int y0 = (int)floorf(fy); if (y0 > IH - 1) y0 = IH - 1;
    int x0 = (int)floorf(fx); if (x0 > IH - 1) x0 = IH - 1;
    int y1 = min(y0 + 1, IH - 1);
    int x1 = min(x0 + 1, IH - 1);
    float wy = fy - (float)y0;
    float wx = fx - (float)x0;
    const float* p = src + (size_t)bc * IHW;
    float v00 = p[y0 * IH + x0], v01 = p[y0 * IH + x1];
    float v10 = p[y1 * IH + x0], v11 = p[y1 * IH + x1];
    float r0 = v00 * (1.0f - wy) + v10 * wy;
    float r1 = v01 * (1.0f - wy) + v11 * wy;
    dst[i] = r0 * (1.0f - wx) + r1 * wx;
}

// ---------------- mask maxpool 2x2 s2 ----------------
__global__ void mpool_k(const float* __restrict__ mask) {
    int idx = blockIdx.x * blockDim.x + threadIdx.x;
    if (idx >= BATCH * HW) return;
    int b = idx / HW, q = idx % HW;
    int y = q / OHW, x = q % OHW;
    const float* p = mask + (size_t)b * IHW;
    float m0 = p[(2*y)   * IH + 2*x], m1 = p[(2*y)   * IH + 2*x + 1];
    float m2 = p[(2*y+1) * IH + 2*x], m3 = p[(2*y+1) * IH + 2*x + 1];
    g_mpool[idx] = fmaxf(fmaxf(m0, m1), fmaxf(m2, m3));
}

// ---------------- pack branch weights ----------------
__global__ void pack_k(const float* __restrict__ W1,  const float* __restrict__ b1,
                       const float* __restrict__ W2a, const float* __restrict__ b2a,
                       const float* __restrict__ W3a, const float* __restrict__ b3a) {
    int idx = blockIdx.x * blockDim.x + threadIdx.x;
    if (idx < MFUSE * HW) {
        int m = idx / HW, k = idx % HW;
        float v;
        if (m < 128)      v = W1 [(size_t)m * HW + k];
        else if (m < 320) v = W2a[(size_t)(m - 128) * HW + k];
        else              v = W3a[(size_t)(m - 320) * HW + k];
        g_Wpk[idx] = v;
    }
    if (idx < MFUSE) {
        float v;
        if (idx < 128)      v = b1 [idx];
        else if (idx < 320) v = b2a[idx - 128];
        else                v = b3a[idx - 320];
        g_bpk[idx] = v;
    }
}

// ---------------- bf16 split helpers ----------------
__device__ __forceinline__ void bsplit(float v, float& hf, float& rf) {
    __nv_bfloat16 h = __float2bfloat16(v);
    hf = __bfloat162float(h);
    rf = v - hf;
}
// pack: low half = e (even k), high half = o (odd k)
__device__ __forceinline__ uint32_t packb(float e, float o) {
    uint32_t r;
    asm("cvt.rn.bf16x2.f32 %0, %1, %2;" : "=r"(r) : "f"(o), "f"(e));
    return r;
}

#define MMA_BF16(d, a, b)                                                      \
    asm volatile("mma.sync.aligned.m16n8k16.row.col.f32.bf16.bf16.f32 "        \
        "{%0,%1,%2,%3}, {%4,%5,%6,%7}, {%8,%9}, {%0,%1,%2,%3};"                \
        : "+f"((d)[0]), "+f"((d)[1]), "+f"((d)[2]), "+f"((d)[3])               \
        : "r"((a)[0]), "r"((a)[1]), "r"((a)[2]), "r"((a)[3]),                  \
          "r"((b)[0]), "r"((b)[1]))

// =====================================================================
// 128x128xK16 double-buffered GEMM, 256 threads, bf16 3-pass tensor core.
// smem holds k-pair-packed bf16x2 hi/lo planes, stride 136 (conflict-free).
// C[b][m][n] = relu( epiScale?[b][n] * (sum_k A.B) + bias?[m] )
// MODE: 0 plain B[k][n]; 3/5 conv im2col; 9 fused 3x3 maxpool of scaled corr
// WA: true -> A weights [m][k]; false -> A[k][m]
// ROUTE: true -> A = g_Wpk, bias = g_bpk, outputs routed to y/y2a/y3a
// =====================================================================
template <int MODE, bool WA, bool ROUTE>
__global__ __launch_bounds__(256)
void gemm_k(const float* __restrict__ A, const float* __restrict__ Bm,
            float* __restrict__ C,
            int M, int N, int K,
            long aB, long bB, long cB,
            int sAk, int sAm,
            const float* __restrict__ scale,
            const float* __restrict__ bias,
            int cStride)
{
    const int b = blockIdx.z;
    const float* Ab = ROUTE ? g_Wpk : (A + (size_t)b * aB);
    const float* Bb = Bm + (size_t)b * bB;
    float*       Cb = C  + (size_t)b * cB;
    const float* scb = scale ? scale + (size_t)b * HW : (const float*)0;

    const int m0 = blockIdx.y * 128;
    const int n0 = blockIdx.x * 128;

    __shared__ uint32_t As_hi[2][8][136];
    __shared__ uint32_t As_lo[2][8][136];
    __shared__ uint32_t Bs_hi[2][8][136];
    __shared__ uint32_t Bs_lo[2][8][136];

    const int tid  = threadIdx.x;
    const int wid  = tid >> 5;
    const int lane = tid & 31;
    const int gid  = lane >> 2;      // 0..7
    const int tig  = lane & 3;       // 0..3
    const int wm   = (wid & 1) * 64;
    const int wn   = (wid >> 1) * 32;

    // loader indices
    const int a_k2 = tid >> 5;            // WA=false: k-pair row 0..7
    const int a_m4 = (tid & 31) * 4;
    const int aw_m = tid >> 1;            // WA=true: m row
    const int aw_k = (tid & 1) * 8;       // WA=true: k offset 0 or 8
    const int b_k2 = tid >> 5;
    const int b_n4 = (tid & 31) * 4;

    float4 ar0, ar1, br0, br1;
    const float4 f4z = make_float4(0.f, 0.f, 0.f, 0.f);

#define LOAD_A(K0)                                                              \
    {                                                                           \
        if (WA) {                                                               \
            ar0 = f4z; ar1 = f4z;                                               \
            if (m0 + aw_m < M) {                                                \
                const float* ap = Ab + (size_t)(m0 + aw_m) * sAm + (K0) + aw_k; \
                ar0 = *(const float4*)(ap);                                     \
                ar1 = *(const float4*)(ap + 4);                                 \
            }                                                                   \
        } else {                                                                \
            ar0 = f4z; ar1 = f4z;                                               \
            if (m0 + a_m4 < M) {                                                \
                const float* ap = Ab + (size_t)((K0) + 2 * a_k2) * sAk + m0 + a_m4; \
                ar0 = *(const float4*)(ap);                                     \
                ar1 = *(const float4*)(ap + sAk);                               \
            }                                                                   \
        }                                                                       \
    }

#define STORE_A(BUF)                                                            \
    {                                                                           \
        if (WA) {                                                               \
            float h0,r0v,h1,r1v,h2,r2v,h3,r3v,h4,r4v,h5,r5v,h6,r6v,h7,r7v;      \
            bsplit(ar0.x, h0, r0v); bsplit(ar0.y, h1, r1v);                     \
            bsplit(ar0.z, h2, r2v); bsplit(ar0.w, h3, r3v);                     \
            bsplit(ar1.x, h4, r4v); bsplit(ar1.y, h5, r5v);                     \
            bsplit(ar1.z, h6, r6v); bsplit(ar1.w, h7, r7v);                     \
            int R = aw_k >> 1;                                                  \
            As_hi[BUF][R + 0][aw_m] = packb(h0, h1);                            \
            As_hi[BUF][R + 1][aw_m] = packb(h2, h3);                            \
            As_hi[BUF][R + 2][aw_m] = packb(h4, h5);                            \
            As_hi[BUF][R + 3][aw_m] = packb(h6, h7);                            \
            As_lo[BUF][R + 0][aw_m] = packb(r0v, r1v);                          \
            As_lo[BUF][R + 1][aw_m] = packb(r2v, r3v);                          \
            As_lo[BUF][R + 2][aw_m] = packb(r4v, r5v);                          \
            As_lo[BUF][R + 3][aw_m] = packb(r6v, r7v);                          \
        } else {                                                                \
            float he[4], re[4], ho[4], ro[4];                                   \
            bsplit(ar0.x, he[0], re[0]); bsplit(ar0.y, he[1], re[1]);           \
            bsplit(ar0.z, he[2], re[2]); bsplit(ar0.w, he[3], re[3]);           \
            bsplit(ar1.x, ho[0], ro[0]); bsplit(ar1.y, ho[1], ro[1]);           \
            bsplit(ar1.z, ho[2], ro[2]); bsplit(ar1.w, ho[3], ro[3]);           \
            uint4 hv = make_uint4(packb(he[0], ho[0]), packb(he[1], ho[1]),     \
                                  packb(he[2], ho[2]), packb(he[3], ho[3]));    \
            uint4 lv = make_uint4(packb(re[0], ro[0]), packb(re[1], ro[1]),     \
                                  packb(re[2], ro[2]), packb(re[3], ro[3]));    \
            *(uint4*)&As_hi[BUF][a_k2][a_m4] = hv;                              \
            *(uint4*)&As_lo[BUF][a_k2][a_m4] = lv;                              \
        }                                                                       \
    }

#define LOAD_B(K0)                                                              \
    {                                                                           \
        const int gk = (K0) + 2 * b_k2;                                         \
        const int gn = n0 + b_n4;                                               \
        br0 = f4z; br1 = f4z;                                                   \
        if (gn < N) {                                                           \
            if (MODE == 0) {                                                    \
                const float* bp = Bb + (size_t)gk * N + gn;                     \
                br0 = *(const float4*)(bp);                                     \
                br1 = *(const float4*)(bp + N);                                 \
            } else if (MODE == 9) {                                             \
                const float* row0 = Bb + (size_t)gk * HW;                       \
                const float* row1 = row0 + HW;                                  \
                float v0[4], v1[4];                                             \
                _Pragma("unroll")                                               \
                for (int j = 0; j < 4; j++) {                                   \
                    int nn = gn + j;                                            \
                    int y = nn / OHW, x = nn % OHW;                             \
                    float mx0 = -INFINITY, mx1 = -INFINITY;                     \
                    _Pragma("unroll")                                           \
                    for (int dy = -1; dy <= 1; dy++) {                          \
                        int iy = y + dy;                                        \
                        if (iy < 0 || iy >= OHW) continue;                      \
                        _Pragma("unroll")                                       \
                        for (int dx = -1; dx <= 1; dx++) {                      \
                            int ix = x + dx;                                    \
                            if (ix < 0 || ix >= OHW) continue;                  \
                            int qq = iy * OHW + ix;                             \
                            float sv = scb[qq];                                 \
                            mx0 = fmaxf(mx0, row0[qq] * sv);                    \
                            mx1 = fmaxf(mx1, row1[qq] * sv);                    \
                        }                                                       \
                    }                                                           \
                    v0[j] = mx0; v1[j] = mx1;                                   \
                }                                                               \
                br0 = make_float4(v0[0], v0[1], v0[2], v0[3]);                  \
                br1 = make_float4(v1[0], v1[1], v1[2], v1[3]);                  \
            } else {                                                            \
                const int kk2 = MODE * MODE;                                    \
                const int pad = MODE / 2;                                       \
                float v0[4], v1[4];                                             \
                _Pragma("unroll")                                               \
                for (int rr = 0; rr < 2; rr++) {                                \
                    int gkk = gk + rr;                                          \
                    int c  = gkk / kk2, r2 = gkk % kk2;                         \
                    int ky = r2 / MODE, kx = r2 % MODE;                         \
                    float* vv = rr ? v1 : v0;                                   \
                    _Pragma("unroll")                                           \
                    for (int j = 0; j < 4; j++) {                               \
                        int nn = gn + j;                                        \
                        int yy = nn / OHW + ky - pad;                           \
                        int xx = nn % OHW + kx - pad;                           \
                        float e = 0.0f;                                         \
                        if (yy >= 0 && yy < OHW && xx >= 0 && xx < OHW)         \
                            e = Bb[(size_t)c * HW + yy * OHW + xx];             \
                        vv[j] = e;                                              \
                    }                                                           \
                }                                                               \
                br0 = make_float4(v0[0], v0[1], v0[2], v0[3]);                  \
                br1 = make_float4(v1[0], v1[1], v1[2], v1[3]);                  \
            }                                                                   \
        }                                                                       \
    }

#define STORE_B(BUF)                                                            \
    {                                                                           \
        float he[4], re[4], ho[4], ro[4];                                       \
        bsplit(br0.x, he[0], re[0]); bsplit(br0.y, he[1], re[1]);               \
        bsplit(br0.z, he[2], re[2]); bsplit(br0.w, he[3], re[3]);               \
        bsplit(br1.x, ho[0], ro[0]); bsplit(br1.y, ho[1], ro[1]);               \
        bsplit(br1.z, ho[2], ro[2]); bsplit(br1.w, ho[3], ro[3]);               \
        uint4 hv = make_uint4(packb(he[0], ho[0]), packb(he[1], ho[1]),         \
                              packb(he[2], ho[2]), packb(he[3], ho[3]));        \
        uint4 lv = make_uint4(packb(re[0], ro[0]), packb(re[1], ro[1]),         \
                              packb(re[2], ro[2]), packb(re[3], ro[3]));        \
        *(uint4*)&Bs_hi[BUF][b_k2][b_n4] = hv;                                  \
        *(uint4*)&Bs_lo[BUF][b_k2][b_n4] = lv;                                  \
    }

    float d[4][4][4];
#pragma unroll
    for (int i = 0; i < 4; i++)
#pragma unroll
        for (int j = 0; j < 4; j++)
#pragma unroll
            for (int r = 0; r < 4; r++) d[i][j][r] = 0.0f;

    const int nt = K >> 4;

    LOAD_A(0); LOAD_B(0);
    STORE_A(0); STORE_B(0);
    __syncthreads();

    for (int t = 0; t < nt; t++) {
        const int buf = t & 1;
        if (t + 1 < nt) { LOAD_A((t + 1) * 16); LOAD_B((t + 1) * 16); }

        uint32_t ahi[4][4], alo[4][4], bhi[4][2], blo[4][2];
#pragma unroll
        for (int mf = 0; mf < 4; mf++) {
            int mb = wm + mf * 16 + gid;
            ahi[mf][0] = As_hi[buf][tig    ][mb];
            ahi[mf][1] = As_hi[buf][tig    ][mb + 8];
            ahi[mf][2] = As_hi[buf][tig + 4][mb];
            ahi[mf][3] = As_hi[buf][tig + 4][mb + 8];
            alo[mf][0] = As_lo[buf][tig    ][mb];
            alo[mf][1] = As_lo[buf][tig    ][mb + 8];
            alo[mf][2] = As_lo[buf][tig + 4][mb];
            alo[mf][3] = As_lo[buf][tig + 4][mb + 8];
        }
#pragma unroll
        for (int nf = 0; nf < 4; nf++) {
            int nb = wn + nf * 8 + gid;
            bhi[nf][0] = Bs_hi[buf][tig    ][nb];
            bhi[nf][1] = Bs_hi[buf][tig + 4][nb];
            blo[nf][0] = Bs_lo[buf][tig    ][nb];
            blo[nf][1] = Bs_lo[buf][tig + 4][nb];
        }

#pragma unroll
        for (int mf = 0; mf < 4; mf++)
#pragma unroll
            for (int nf = 0; nf < 4; nf++) {
                MMA_BF16(d[mf][nf], ahi[mf], bhi[nf]);
                MMA_BF16(d[mf][nf], ahi[mf], blo[nf]);
                MMA_BF16(d[mf][nf], alo[mf], bhi[nf]);
            }

        if (t + 1 < nt) { STORE_A(buf ^ 1); STORE_B(buf ^ 1); }
        __syncthreads();
    }

    // ---- epilogue ----
#pragma unroll
    for (int mf = 0; mf < 4; mf++) {
#pragma unroll
        for (int half = 0; half < 2; half++) {
            int m = m0 + wm + mf * 16 + gid + half * 8;
            if (m >= M) continue;
            float bi;
            float* outp;
            if (ROUTE) {
                bi = g_bpk[m];
                if (m < 128)      outp = g_y   + (size_t)b * 512 * HW + (size_t)m * HW;
                else if (m < 320) outp = g_y2a + (size_t)b * 192 * HW + (size_t)(m - 128) * HW;
                else              outp = g_y3a + (size_t)b *  32 * HW + (size_t)(m - 320) * HW;
            } else {
                bi = bias ? bias[m] : 0.0f;
                outp = Cb + (size_t)m * cStride;
            }
#pragma unroll
            for (int nf = 0; nf < 4; nf++) {
                int n = n0 + wn + nf * 8 + 2 * tig;
                float v0 = d[mf][nf][half * 2 + 0];
                float v1 = d[mf][nf][half * 2 + 1];
                if (n < N) {
                    float v = v0;
                    if (MODE != 9 && scale) v *= scb[n];
                    outp[n] = fmaxf(v + bi, 0.0f);
                }
                if (n + 1 < N) {
                    float v = v1;
                    if (MODE != 9 && scale) v *= scb[n + 1];
                    outp[n + 1] = fmaxf(v + bi, 0.0f);
                }
            }
        }
    }
#undef LOAD_A
#undef STORE_A
#undef LOAD_B
#undef STORE_B
}

// ---------------- per-column L2 norm of corr -> scale ----------------
__global__ void norm_k() {
    int idx = blockIdx.x * blockDim.x + threadIdx.x;
    if (idx >= BATCH * HW) return;
    int b = idx / HW, q = idx % HW;
    const float* base = g_corr + (size_t)b * HW * HW + q;
    float s0 = 0.f, s1 = 0.f, s2 = 0.f, s3 = 0.f;
    for (int p = 0; p + 4 <= HW; p += 4) {
        float v0 = base[(size_t)(p    ) * HW];
        float v1 = base[(size_t)(p + 1) * HW];
        float v2 = base[(size_t)(p + 2) * HW];
        float v3 = base[(size_t)(p + 3) * HW];
        s0 += v0 * v0; s1 += v1 * v1; s2 += v2 * v2; s3 += v3 * v3;
    }
    float s = (s0 + s1) + (s2 + s3);
    g_scale[idx] = g_mpool[idx] / sqrtf(s);
}

// ---------------- batchnorm ----------------
__global__ void bnstat_k() {
    const int ch  = blockIdx.x;
    const int tid = threadIdx.x;
    const int NEL = BATCH * HW;
    double s = 0.0, ss = 0.0;
    for (int i = tid; i < NEL; i += blockDim.x) {
        int b = i / HW, q = i % HW;
        float v = g_y[(size_t)b * 512 * HW + (size_t)ch * HW + q];
        s  += (double)v;
        ss += (double)v * (double)v;
    }
    __shared__ double sh[256];
    __shared__ double sh2[256];
    sh[tid] = s; sh2[tid] = ss;
    __syncthreads();
    for (int st = 128; st > 0; st >>= 1) {
        if (tid < st) { sh[tid] += sh[tid + st]; sh2[tid] += sh2[tid + st]; }
        __syncthreads();
    }
    if (tid == 0) {
        double mean = sh[0] / NEL;
        double var  = sh2[0] / NEL - mean * mean;
        g_mean[ch] = (float)mean;
        g_inv[ch]  = (float)(1.0 / sqrt(var + 1e-5));
    }
}

__global__ void bnapply_k(const float* __restrict__ gamma,
                          const float* __restrict__ beta,
                          float* __restrict__ out) {
    int idx = blockIdx.x * blockDim.x + threadIdx.x;
    if (idx >= BATCH * 512 * HW) return;
    int ch = (idx / HW) % 512;
    out[idx] = gamma[ch] * (g_y[idx] - g_mean[ch]) * g_inv[ch] + beta[ch];
}

// ---------------- launch ----------------
static float* sym_addr(const void* symbol) {
    void* p = nullptr;
    cudaGetSymbolAddress(&p, symbol);
    return (float*)p;
}

extern "C" void kernel_launch(void* const* d_in, const int* in_sizes, int n_in,
                              void* d_out, int out_size) {
    const float* feature1 = (const float*)d_in[0];
    const float* feature2 = (const float*)d_in[1];
    const float* mask     = (const float*)d_in[2];
    const float* W1  = (const float*)d_in[3];
    const float* b1  = (const float*)d_in[4];
    const float* W2a = (const float*)d_in[5];
    const float* b2a = (const float*)d_in[6];
    const float* W2b = (const float*)d_in[7];
    const float* b2b = (const float*)d_in[8];
    const float* W3a = (const float*)d_in[9];
    const float* b3a = (const float*)d_in[10];
    const float* W3b = (const float*)d_in[11];
    const float* b3b = (const float*)d_in[12];
    const float* W4  = (const float*)d_in[13];
    const float* b4  = (const float*)d_in[14];
    const float* gamma = (const float*)d_in[15];
    const float* beta  = (const float*)d_in[16];
    float* out = (float*)d_out;

    float* f1r  = sym_addr(g_f1r);
    float* f2r  = sym_addr(g_f2r);
    float* corr = sym_addr(g_corr);
    float* scal = sym_addr(g_scale);
    float* y2a  = sym_addr(g_y2a);
    float* y3a  = sym_addr(g_y3a);
    float* ybuf = sym_addr(g_y);

    // 1) resize
    {
        int total = 2 * BATCH * CIN * HW;
        resize_k<<<(total + 255) / 256, 256>>>(feature1, feature2);
    }
    // 2) mask maxpool + weight packing
    mpool_k<<<(BATCH * HW + 255) / 256, 256>>>(mask);
    pack_k<<<(MFUSE * HW + 255) / 256, 256>>>(W1, b1, W2a, b2a, W3a, b3a);

    // 3) correlation GEMM: corr[b][p][q] = relu(sum_c f1r[b][c][p] * f2r[b][c][q])
    gemm_k<0, false, false><<<dim3(7, 7, BATCH), 256>>>(
        f1r, f2r, corr, HW, HW, CIN,
        (long)CIN * HW, (long)CIN * HW, (long)HW * HW,
        HW, 1, nullptr, nullptr, HW);

    // 4) column L2 norm -> scale
    norm_k<<<(BATCH * HW + 255) / 256, 256>>>();

    // 5) fused 1x1 branches (M=352), scale folded in epilogue
    gemm_k<0, true, true><<<dim3(7, 3, BATCH), 256>>>(
        nullptr, corr, nullptr, MFUSE, HW, HW,
        0L, (long)HW * HW, 0L,
        1, HW, scal, nullptr, HW);

    // 6) W4 on 3x3-maxpooled scaled corr (pool fused in loader)
    gemm_k<9, true, false><<<dim3(7, 1, BATCH), 256>>>(
        W4, corr, ybuf + (size_t)448 * HW, 64, HW, HW,
        0L, (long)HW * HW, (long)512 * HW,
        1, HW, scal, b4, HW);

    // 7) 3x3 conv 192->256
    gemm_k<3, true, false><<<dim3(7, 2, BATCH), 256>>>(
        W2b, y2a, ybuf + (size_t)128 * HW, 256, HW, 192 * 9,
        0L, (long)192 * HW, (long)512 * HW,
        1, 192 * 9, nullptr, b2b, HW);

    // 8) 5x5 conv 32->64
    gemm_k<5, true, false><<<dim3(7, 1, BATCH), 256>>>(
        W3b, y3a, ybuf + (size_t)384 * HW, 64, HW, 32 * 25,
        0L, (long)32 * HW, (long)512 * HW,
        1, 32 * 25, nullptr, b3b, HW);

    // 9) batchnorm
    bnstat_k<<<512, 256>>>();
    bnapply_k<<<(BATCH * 512 * HW + 255) / 256, 256>>>(gamma, beta, out);
}

// round 12
// speedup vs baseline: 2.0423x; 1.1726x over previous
#include <cuda_runtime.h>
#include <cuda_bf16.h>
#include <math.h>
#include <stdint.h>

#define BATCH 32
#define CIN   256
#define OHW   28
#define HW    784          // 28*28
#define IH    56
#define IHW   3136         // 56*56
#define MFUSE 352          // 128 + 192 + 32

// ---------------- scratch ----------------
// packed bf16x2 hi/lo planes: [b][kp][col], value pair (k=2kp, 2kp+1)
__device__ __align__(16) uint32_t g_f1h[BATCH * 128 * HW];
__device__ __align__(16) uint32_t g_f1l[BATCH * 128 * HW];
__device__ __align__(16) uint32_t g_f2h[BATCH * 128 * HW];
__device__ __align__(16) uint32_t g_f2l[BATCH * 128 * HW];
__device__ __align__(16) uint32_t g_Wph [392 * MFUSE];
__device__ __align__(16) uint32_t g_Wpl [392 * MFUSE];
__device__ __align__(16) uint32_t g_W2bh[864 * 256];
__device__ __align__(16) uint32_t g_W2bl[864 * 256];
__device__ __align__(16) uint32_t g_W3bh[400 * 64];
__device__ __align__(16) uint32_t g_W3bl[400 * 64];
__device__ __align__(16) uint32_t g_W4h [392 * 64];
__device__ __align__(16) uint32_t g_W4l [392 * 64];
__device__ float g_mpool[BATCH * HW];
__device__ float g_scale[BATCH * HW];
__device__ float g_corr [(size_t)BATCH * HW * HW];
__device__ float g_y2a  [BATCH * 192 * HW];
__device__ float g_y3a  [BATCH *  32 * HW];
__device__ float g_y    [BATCH * 512 * HW];
__device__ float g_mean [512];
__device__ float g_inv  [512];
__device__ float g_bpk  [MFUSE];

// ---------------- bf16 split helpers ----------------
__device__ __forceinline__ void bsplit(float v, float& hf, float& rf) {
    __nv_bfloat16 h = __float2bfloat16(v);
    hf = __bfloat162float(h);
    rf = v - hf;
}
__device__ __forceinline__ uint32_t packb(float e, float o) {
    uint32_t r;
    asm("cvt.rn.bf16x2.f32 %0, %1, %2;" : "=r"(r) : "f"(o), "f"(e));
    return r;
}

// ---------------- resize 56->28 align_corners + split/pack to planes ----------------
__global__ void resize_pack_k(const float* __restrict__ f1, const float* __restrict__ f2) {
    int idx = blockIdx.x * blockDim.x + threadIdx.x;
    const int per = BATCH * 128 * HW;
    if (idx >= 2 * per) return;
    int f = idx >= per;
    int i = idx - f * per;
    const float* src = f ? f2 : f1;
    uint32_t* dsth   = f ? g_f2h : g_f1h;
    uint32_t* dstl   = f ? g_f2l : g_f1l;
    int q  = i % HW;
    int t  = i / HW;
    int cp = t % 128;
    int b  = t / 128;
    int oy = q / OHW, ox = q % OHW;
    const float step = 55.0f / 27.0f;
    float fy = oy * step, fx = ox * step;
    int y0 = (int)floorf(fy); if (y0 > IH - 1) y0 = IH - 1;
    int x0 = (int)floorf(fx); if (x0 > IH - 1) x0 = IH - 1;
    int y1 = min(y0 + 1, IH - 1);
    int x1 = min(x0 + 1, IH - 1);
    float wy = fy - (float)y0;
    float wx = fx - (float)x0;
    const float* p0 = src + ((size_t)b * CIN + 2 * cp) * IHW;
    const float* p1 = p0 + IHW;
    float v00 = p0[y0 * IH + x0], v01 = p0[y0 * IH + x1];
    float v10 = p0[y1 * IH + x0], v11 = p0[y1 * IH + x1];
    float a0 = (v00 * (1.0f - wy) + v10 * wy) * (1.0f - wx)
             + (v01 * (1.0f - wy) + v11 * wy) * wx;
    v00 = p1[y0 * IH + x0]; v01 = p1[y0 * IH + x1];
    v10 = p1[y1 * IH + x0]; v11 = p1[y1 * IH + x1];
    float a1 = (v00 * (1.0f - wy) + v10 * wy) * (1.0f - wx)
             + (v01 * (1.0f - wy) + v11 * wy) * wx;
    float h0, r0, h1, r1;
    bsplit(a0, h0, r0); bsplit(a1, h1, r1);
    size_t o = ((size_t)b * 128 + cp) * HW + q;
    dsth[o] = packb(h0, h1);
    dstl[o] = packb(r0, r1);
}

// ---------------- mask maxpool 2x2 s2 ----------------
__global__ void mpool_k(const float* __restrict__ mask) {
    int idx = blockIdx.x * blockDim.x + threadIdx.x;
    if (idx >= BATCH * HW) return;
    int b = idx / HW, q = idx % HW;
    int y = q / OHW, x = q % OHW;
    const float* p = mask + (size_t)b * IHW;
    float m0 = p[(2*y)   * IH + 2*x], m1 = p[(2*y)   * IH + 2*x + 1];
    float m2 = p[(2*y+1) * IH + 2*x], m3 = p[(2*y+1) * IH + 2*x + 1];
    g_mpool[idx] = fmaxf(fmaxf(m0, m1), fmaxf(m2, m3));
}

// ---------------- pack all weights into bf16 planes ----------------
#define NP1 (392 * MFUSE)
#define NP2 (864 * 256)
#define NP3 (400 * 64)
#define NP4 (392 * 64)
__global__ void packw_k(const float* __restrict__ W1,  const float* __restrict__ b1,
                        const float* __restrict__ W2a, const float* __restrict__ b2a,
                        const float* __restrict__ W3a, const float* __restrict__ b3a,
                        const float* __restrict__ W2b, const float* __restrict__ W3b,
                        const float* __restrict__ W4) {
    int idx = blockIdx.x * blockDim.x + threadIdx.x;
    if (idx < MFUSE) {
        float v;
        if (idx < 128)      v = b1 [idx];
        else if (idx < 320) v = b2a[idx - 128];
        else                v = b3a[idx - 320];
        g_bpk[idx] = v;
    }
    float v0, v1;
    uint32_t* dh; uint32_t* dl; size_t o;
    if (idx < NP1) {
        int kp = idx / MFUSE, m = idx % MFUSE;
        const float* w;
        if (m < 128)      w = W1  + (size_t)m * HW;
        else if (m < 320) w = W2a + (size_t)(m - 128) * HW;
        else              w = W3a + (size_t)(m - 320) * HW;
        v0 = w[2 * kp]; v1 = w[2 * kp + 1];
        dh = g_Wph; dl = g_Wpl; o = (size_t)kp * MFUSE + m;
    } else if (idx < NP1 + NP2) {
        int j = idx - NP1;
        int kp = j / 256, m = j % 256;
        v0 = W2b[(size_t)m * 1728 + 2 * kp]; v1 = W2b[(size_t)m * 1728 + 2 * kp + 1];
        dh = g_W2bh; dl = g_W2bl; o = (size_t)kp * 256 + m;
    } else if (idx < NP1 + NP2 + NP3) {
        int j = idx - NP1 - NP2;
        int kp = j / 64, m = j % 64;
        v0 = W3b[(size_t)m * 800 + 2 * kp]; v1 = W3b[(size_t)m * 800 + 2 * kp + 1];
        dh = g_W3bh; dl = g_W3bl; o = (size_t)kp * 64 + m;
    } else if (idx < NP1 + NP2 + NP3 + NP4) {
        int j = idx - NP1 - NP2 - NP3;
        int kp = j / 64, m = j % 64;
        v0 = W4[(size_t)m * HW + 2 * kp]; v1 = W4[(size_t)m * HW + 2 * kp + 1];
        dh = g_W4h; dl = g_W4l; o = (size_t)kp * 64 + m;
    } else return;
    float h0, r0, h1, r1;
    bsplit(v0, h0, r0); bsplit(v1, h1, r1);
    dh[o] = packb(h0, h1);
    dl[o] = packb(r0, r1);
}

#define MMA_BF16(d, a, b)                                                      \
    asm volatile("mma.sync.aligned.m16n8k16.row.col.f32.bf16.bf16.f32 "        \
        "{%0,%1,%2,%3}, {%4,%5,%6,%7}, {%8,%9}, {%0,%1,%2,%3};"                \
        : "+f"((d)[0]), "+f"((d)[1]), "+f"((d)[2]), "+f"((d)[3])               \
        : "r"((a)[0]), "r"((a)[1]), "r"((a)[2]), "r"((a)[3]),                  \
          "r"((b)[0]), "r"((b)[1]))

// =====================================================================
// 128x128xK16 double-buffered GEMM, 256 threads, bf16 3-pass tensor core.
// A always pre-split planes. B:
//   MODE 0 = pre-split planes (corr GEMM)
//   MODE 1 = plain fp32 B[k][n] (branch GEMM from corr)
//   MODE 3/5 = conv im2col decode from fp32
//   MODE 9 = fused 3x3 maxpool of scaled corr
// ROUTE: bias = g_bpk, outputs routed to y/y2a/y3a
// =====================================================================
template <int MODE, bool ROUTE>
__global__ __launch_bounds__(256)
void gemm_k(const uint32_t* __restrict__ Ah, const uint32_t* __restrict__ Al,
            long aB, int aS, int M,
            const uint32_t* __restrict__ Bph, const uint32_t* __restrict__ Bpl,
            const float* __restrict__ Bf, long bB,
            float* __restrict__ C, long cB, int cStride,
            int N, int K,
            const float* __restrict__ scale, const float* __restrict__ bias)
{
    const int b = blockIdx.z;
    const uint32_t* Ahb = Ah + (size_t)b * aB;
    const uint32_t* Alb = Al + (size_t)b * aB;
    const uint32_t* Bphb = (MODE == 0) ? (Bph + (size_t)b * bB) : (const uint32_t*)0;
    const uint32_t* Bplb = (MODE == 0) ? (Bpl + (size_t)b * bB) : (const uint32_t*)0;
    const float*    Bfb  = (MODE != 0) ? (Bf  + (size_t)b * bB) : (const float*)0;
    const float* scb = scale ? scale + (size_t)b * HW : (const float*)0;

    const int m0 = blockIdx.y * 128;
    const int n0 = blockIdx.x * 128;

    __shared__ uint32_t As_hi[2][8][136];
    __shared__ uint32_t As_lo[2][8][136];
    __shared__ uint32_t Bs_hi[2][8][136];
    __shared__ uint32_t Bs_lo[2][8][136];

    const int tid  = threadIdx.x;
    const int wid  = tid >> 5;
    const int lane = tid & 31;
    const int gid  = lane >> 2;
    const int tig  = lane & 3;
    const int wm   = (wid & 1) * 64;
    const int wn   = (wid >> 1) * 32;

    const int a_k2 = tid >> 5;            // k-pair row 0..7
    const int a_m4 = (tid & 31) * 4;
    const int b_k2 = tid >> 5;
    const int b_n4 = (tid & 31) * 4;

    uint4 avh, avl, bvh, bvl;
    float4 br0, br1;
    const uint4  z4  = make_uint4(0u, 0u, 0u, 0u);
    const float4 f4z = make_float4(0.f, 0.f, 0.f, 0.f);

#define LOAD_A(K0)                                                              \
    {                                                                           \
        avh = z4; avl = z4;                                                     \
        if (m0 + a_m4 < M) {                                                    \
            size_t o = (size_t)((((K0) >> 1)) + a_k2) * aS + m0 + a_m4;         \
            avh = *(const uint4*)(Ahb + o);                                     \
            avl = *(const uint4*)(Alb + o);                                     \
        }                                                                       \
    }
#define STORE_A(BUF)                                                            \
    {                                                                           \
        *(uint4*)&As_hi[BUF][a_k2][a_m4] = avh;                                 \
        *(uint4*)&As_lo[BUF][a_k2][a_m4] = avl;                                 \
    }

#define LOAD_B(K0)                                                              \
    {                                                                           \
        if (MODE == 0) {                                                        \
            bvh = z4; bvl = z4;                                                 \
            if (n0 + b_n4 < N) {                                                \
                size_t o = (size_t)((((K0) >> 1)) + b_k2) * N + n0 + b_n4;      \
                bvh = *(const uint4*)(Bphb + o);                                \
                bvl = *(const uint4*)(Bplb + o);                                \
            }                                                                   \
        } else {                                                                \
            const int gk = (K0) + 2 * b_k2;                                     \
            const int gn = n0 + b_n4;                                           \
            br0 = f4z; br1 = f4z;                                               \
            if (gn < N) {                                                       \
                if (MODE == 1) {                                                \
                    const float* bp = Bfb + (size_t)gk * N + gn;                \
                    br0 = *(const float4*)(bp);                                 \
                    br1 = *(const float4*)(bp + N);                             \
                } else if (MODE == 9) {                                         \
                    const float* row0 = Bfb + (size_t)gk * HW;                  \
                    const float* row1 = row0 + HW;                              \
                    float v0[4], v1[4];                                         \
                    _Pragma("unroll")                                           \
                    for (int j = 0; j < 4; j++) {                               \
                        int nn = gn + j;                                        \
                        int y = nn / OHW, x = nn % OHW;                         \
                        float mx0 = -INFINITY, mx1 = -INFINITY;                 \
                        _Pragma("unroll")                                       \
                        for (int dy = -1; dy <= 1; dy++) {                      \
                            int iy = y + dy;                                    \
                            if (iy < 0 || iy >= OHW) continue;                  \
                            _Pragma("unroll")                                   \
                            for (int dx = -1; dx <= 1; dx++) {                  \
                                int ix = x + dx;                                \
                                if (ix < 0 || ix >= OHW) continue;              \
                                int qq = iy * OHW + ix;                         \
                                float sv = scb[qq];                             \
                                mx0 = fmaxf(mx0, row0[qq] * sv);                \
                                mx1 = fmaxf(mx1, row1[qq] * sv);                \
                            }                                                   \
                        }                                                       \
                        v0[j] = mx0; v1[j] = mx1;                               \
                    }                                                           \
                    br0 = make_float4(v0[0], v0[1], v0[2], v0[3]);              \
                    br1 = make_float4(v1[0], v1[1], v1[2], v1[3]);              \
                } else {                                                        \
                    const int kk2 = MODE * MODE;                                \
                    const int pad = MODE / 2;                                   \
                    float v0[4], v1[4];                                         \
                    _Pragma("unroll")                                           \
                    for (int rr = 0; rr < 2; rr++) {                            \
                        int gkk = gk + rr;                                      \
                        int c  = gkk / kk2, r2 = gkk % kk2;                     \
                        int ky = r2 / MODE, kx = r2 % MODE;                     \
                        float* vv = rr ? v1 : v0;                               \
                        _Pragma("unroll")                                       \
                        for (int j = 0; j < 4; j++) {                           \
                            int nn = gn + j;                                    \
                            int yy = nn / OHW + ky - pad;                       \
                            int xx = nn % OHW + kx - pad;                       \
                            float e = 0.0f;                                     \
                            if (yy >= 0 && yy < OHW && xx >= 0 && xx < OHW)     \
                                e = Bfb[(size_t)c * HW + yy * OHW + xx];        \
                            vv[j] = e;                                          \
                        }                                                       \
                    }                                                           \
                    br0 = make_float4(v0[0], v0[1], v0[2], v0[3]);              \
                    br1 = make_float4(v1[0], v1[1], v1[2], v1[3]);              \
                }                                                               \
            }                                                                   \
        }                                                                       \
    }

#define STORE_B(BUF)                                                            \
    {                                                                           \
        if (MODE == 0) {                                                        \
            *(uint4*)&Bs_hi[BUF][b_k2][b_n4] = bvh;                             \
            *(uint4*)&Bs_lo[BUF][b_k2][b_n4] = bvl;                             \
        } else {                                                                \
            float he[4], re[4], ho[4], ro[4];                                   \
            bsplit(br0.x, he[0], re[0]); bsplit(br0.y, he[1], re[1]);           \
            bsplit(br0.z, he[2], re[2]); bsplit(br0.w, he[3], re[3]);           \
            bsplit(br1.x, ho[0], ro[0]); bsplit(br1.y, ho[1], ro[1]);           \
            bsplit(br1.z, ho[2], ro[2]); bsplit(br1.w, ho[3], ro[3]);           \
            uint4 hv = make_uint4(packb(he[0], ho[0]), packb(he[1], ho[1]),     \
                                  packb(he[2], ho[2]), packb(he[3], ho[3]));    \
            uint4 lv = make_uint4(packb(re[0], ro[0]), packb(re[1], ro[1]),     \
                                  packb(re[2], ro[2]), packb(re[3], ro[3]));    \
            *(uint4*)&Bs_hi[BUF][b_k2][b_n4] = hv;                              \
            *(uint4*)&Bs_lo[BUF][b_k2][b_n4] = lv;                              \
        }                                                                       \
    }

    float d[4][4][4];
#pragma unroll
    for (int i = 0; i < 4; i++)
#pragma unroll
        for (int j = 0; j < 4; j++)
#pragma unroll
            for (int r = 0; r < 4; r++) d[i][j][r] = 0.0f;

    const int nt = K >> 4;

    LOAD_A(0); LOAD_B(0);
    STORE_A(0); STORE_B(0);
    __syncthreads();

    for (int t = 0; t < nt; t++) {
        const int buf = t & 1;
        if (t + 1 < nt) { LOAD_A((t + 1) * 16); LOAD_B((t + 1) * 16); }

        uint32_t ahi[4][4], alo[4][4], bhi[4][2], blo[4][2];
#pragma unroll
        for (int mf = 0; mf < 4; mf++) {
            int mb = wm + mf * 16 + gid;
            ahi[mf][0] = As_hi[buf][tig    ][mb];
            ahi[mf][1] = As_hi[buf][tig    ][mb + 8];
            ahi[mf][2] = As_hi[buf][tig + 4][mb];
            ahi[mf][3] = As_hi[buf][tig + 4][mb + 8];
            alo[mf][0] = As_lo[buf][tig    ][mb];
            alo[mf][1] = As_lo[buf][tig    ][mb + 8];
            alo[mf][2] = As_lo[buf][tig + 4][mb];
            alo[mf][3] = As_lo[buf][tig + 4][mb + 8];
        }
#pragma unroll
        for (int nf = 0; nf < 4; nf++) {
            int nb = wn + nf * 8 + gid;
            bhi[nf][0] = Bs_hi[buf][tig    ][nb];
            bhi[nf][1] = Bs_hi[buf][tig + 4][nb];
            blo[nf][0] = Bs_lo[buf][tig    ][nb];
            blo[nf][1] = Bs_lo[buf][tig + 4][nb];
        }

#pragma unroll
        for (int mf = 0; mf < 4; mf++)
#pragma unroll
            for (int nf = 0; nf < 4; nf++) {
                MMA_BF16(d[mf][nf], ahi[mf], bhi[nf]);
                MMA_BF16(d[mf][nf], ahi[mf], blo[nf]);
                MMA_BF16(d[mf][nf], alo[mf], bhi[nf]);
            }

        if (t + 1 < nt) { STORE_A(buf ^ 1); STORE_B(buf ^ 1); }
        __syncthreads();
    }

    // ---- epilogue ----
#pragma unroll
    for (int mf = 0; mf < 4; mf++) {
#pragma unroll
        for (int half = 0; half < 2; half++) {
            int m = m0 + wm + mf * 16 + gid + half * 8;
            if (m >= M) continue;
            float bi;
            float* outp;
            if (ROUTE) {
                bi = g_bpk[m];
                if (m < 128)      outp = g_y   + (size_t)b * 512 * HW + (size_t)m * HW;
                else if (m < 320) outp = g_y2a + (size_t)b * 192 * HW + (size_t)(m - 128) * HW;
                else              outp = g_y3a + (size_t)b *  32 * HW + (size_t)(m - 320) * HW;
            } else {
                bi = bias ? bias[m] : 0.0f;
                outp = C + (size_t)b * cB + (size_t)m * cStride;
            }
#pragma unroll
            for (int nf = 0; nf < 4; nf++) {
                int n = n0 + wn + nf * 8 + 2 * tig;
                float v0 = d[mf][nf][half * 2 + 0];
                float v1 = d[mf][nf][half * 2 + 1];
                if (n < N) {
                    float v = v0;
                    if (MODE != 9 && scale) v *= scb[n];
                    outp[n] = fmaxf(v + bi, 0.0f);
                }
                if (n + 1 < N) {
                    float v = v1;
                    if (MODE != 9 && scale) v *= scb[n + 1];
                    outp[n + 1] = fmaxf(v + bi, 0.0f);
                }
            }
        }
    }
#undef LOAD_A
#undef STORE_A
#undef LOAD_B
#undef STORE_B
}

// ---------------- per-column L2 norm of corr -> scale ----------------
__global__ void norm_k() {
    int idx = blockIdx.x * blockDim.x + threadIdx.x;
    if (idx >= BATCH * HW) return;
    int b = idx / HW, q = idx % HW;
    const float* base = g_corr + (size_t)b * HW * HW + q;
    float s0 = 0.f, s1 = 0.f, s2 = 0.f, s3 = 0.f;
    for (int p = 0; p + 4 <= HW; p += 4) {
        float v0 = base[(size_t)(p    ) * HW];
        float v1 = base[(size_t)(p + 1) * HW];
        float v2 = base[(size_t)(p + 2) * HW];
        float v3 = base[(size_t)(p + 3) * HW];
        s0 += v0 * v0; s1 += v1 * v1; s2 += v2 * v2; s3 += v3 * v3;
    }
    float s = (s0 + s1) + (s2 + s3);
    g_scale[idx] = g_mpool[idx] / sqrtf(s);
}

// ---------------- batchnorm ----------------
__global__ void bnstat_k() {
    const int ch  = blockIdx.x;
    const int tid = threadIdx.x;
    const int NEL = BATCH * HW;
    double s = 0.0, ss = 0.0;
    for (int i = tid; i < NEL; i += blockDim.x) {
        int b = i / HW, q = i % HW;
        float v = g_y[(size_t)b * 512 * HW + (size_t)ch * HW + q];
        s  += (double)v;
        ss += (double)v * (double)v;
    }
    __shared__ double sh[256];
    __shared__ double sh2[256];
    sh[tid] = s; sh2[tid] = ss;
    __syncthreads();
    for (int st = 128; st > 0; st >>= 1) {
        if (tid < st) { sh[tid] += sh[tid + st]; sh2[tid] += sh2[tid + st]; }
        __syncthreads();
    }
    if (tid == 0) {
        double mean = sh[0] / NEL;
        double var  = sh2[0] / NEL - mean * mean;
        g_mean[ch] = (float)mean;
        g_inv[ch]  = (float)(1.0 / sqrt(var + 1e-5));
    }
}

__global__ void bnapply_k(const float* __restrict__ gamma,
                          const float* __restrict__ beta,
                          float* __restrict__ out) {
    int idx = blockIdx.x * blockDim.x + threadIdx.x;
    if (idx >= BATCH * 512 * HW) return;
    int ch = (idx / HW) % 512;
    out[idx] = gamma[ch] * (g_y[idx] - g_mean[ch]) * g_inv[ch] + beta[ch];
}

// ---------------- launch ----------------
static float* sym_addr_f(const void* symbol) {
    void* p = nullptr;
    cudaGetSymbolAddress(&p, symbol);
    return (float*)p;
}
static uint32_t* sym_addr_u(const void* symbol) {
    void* p = nullptr;
    cudaGetSymbolAddress(&p, symbol);
    return (uint32_t*)p;
}

extern "C" void kernel_launch(void* const* d_in, const int* in_sizes, int n_in,
                              void* d_out, int out_size) {
    const float* feature1 = (const float*)d_in[0];
    const float* feature2 = (const float*)d_in[1];
    const float* mask     = (const float*)d_in[2];
    const float* W1  = (const float*)d_in[3];
    const float* b1  = (const float*)d_in[4];
    const float* W2a = (const float*)d_in[5];
    const float* b2a = (const float*)d_in[6];
    const float* W2b = (const float*)d_in[7];
    const float* b2b = (const float*)d_in[8];
    const float* W3a = (const float*)d_in[9];
    const float* b3a = (const float*)d_in[10];
    const float* W3b = (const float*)d_in[11];
    const float* b3b = (const float*)d_in[12];
    const float* W4  = (const float*)d_in[13];
    const float* b4  = (const float*)d_in[14];
    const float* gamma = (const float*)d_in[15];
    const float* beta  = (const float*)d_in[16];
    float* out = (float*)d_out;

    uint32_t* f1h = sym_addr_u(g_f1h);
    uint32_t* f1l = sym_addr_u(g_f1l);
    uint32_t* f2h = sym_addr_u(g_f2h);
    uint32_t* f2l = sym_addr_u(g_f2l);
    uint32_t* Wph = sym_addr_u(g_Wph);
    uint32_t* Wpl = sym_addr_u(g_Wpl);
    uint32_t* W2bh = sym_addr_u(g_W2bh);
    uint32_t* W2bl = sym_addr_u(g_W2bl);
    uint32_t* W3bh = sym_addr_u(g_W3bh);
    uint32_t* W3bl = sym_addr_u(g_W3bl);
    uint32_t* W4h = sym_addr_u(g_W4h);
    uint32_t* W4l = sym_addr_u(g_W4l);
    float* corr = sym_addr_f(g_corr);
    float* scal = sym_addr_f(g_scale);
    float* y2a  = sym_addr_f(g_y2a);
    float* y3a  = sym_addr_f(g_y3a);
    float* ybuf = sym_addr_f(g_y);

    // 1) resize + split/pack feature planes
    {
        int total = 2 * BATCH * 128 * HW;
        resize_pack_k<<<(total + 255) / 256, 256>>>(feature1, feature2);
    }
    // 2) mask maxpool + weight plane packing
    mpool_k<<<(BATCH * HW + 255) / 256, 256>>>(mask);
    {
        int total = NP1 + NP2 + NP3 + NP4;
        packw_k<<<(total + 255) / 256, 256>>>(W1, b1, W2a, b2a, W3a, b3a, W2b, W3b, W4);
    }

    // 3) correlation GEMM: corr[b][p][q] = relu(sum_c f1[c][p] * f2[c][q])
    gemm_k<0, false><<<dim3(7, 7, BATCH), 256>>>(
        f1h, f1l, (long)128 * HW, HW, HW,
        f2h, f2l, nullptr, (long)128 * HW,
        corr, (long)HW * HW, HW,
        HW, CIN, nullptr, nullptr);

    // 4) column L2 norm -> scale
    norm_k<<<(BATCH * HW + 255) / 256, 256>>>();

    // 5) fused 1x1 branches (M=352), scale in epilogue, routed outputs
    gemm_k<1, true><<<dim3(7, 3, BATCH), 256>>>(
        Wph, Wpl, 0L, MFUSE, MFUSE,
        nullptr, nullptr, corr, (long)HW * HW,
        nullptr, 0L, HW,
        HW, HW, scal, nullptr);

    // 6) W4 on 3x3-maxpooled scaled corr (pool fused in loader)
    gemm_k<9, false><<<dim3(7, 1, BATCH), 256>>>(
        W4h, W4l, 0L, 64, 64,
        nullptr, nullptr, corr, (long)HW * HW,
        ybuf + (size_t)448 * HW, (long)512 * HW, HW,
        HW, HW, scal, b4);

    // 7) 3x3 conv 192->256
    gemm_k<3, false><<<dim3(7, 2, BATCH), 256>>>(
        W2bh, W2bl, 0L, 256, 256,
        nullptr, nullptr, y2a, (long)192 * HW,
        ybuf + (size_t)128 * HW, (long)512 * HW, HW,
        HW, 192 * 9, nullptr, b2b);

    // 8) 5x5 conv 32->64
    gemm_k<5, false><<<dim3(7, 1, BATCH), 256>>>(
        W3bh, W3bl, 0L, 64, 64,
        nullptr, nullptr, y3a, (long)32 * HW,
        ybuf + (size_t)384 * HW, (long)512 * HW, HW,
        HW, 32 * 25, nullptr, b3b);

    // 9) batchnorm
    bnstat_k<<<512, 256>>>();
    bnapply_k<<<(BATCH * 512 * HW + 255) / 256, 256>>>(gamma, beta, out);
}